// round 16
// baseline (speedup 1.0000x reference)
#include <cuda_runtime.h>
#include <cuda_fp16.h>
#include <cstdint>

#define NCELLS 131072
#define MC     64
#define NBLK   (NCELLS/MC)   // 2048
#define DC     4096

// ---------------- device scratch ----------------
__device__ __align__(16) uint2 d_W1h[16*32*32];        // stage1 B frags (fp16)
__device__ __align__(16) uint2 d_W2h[16*16*32];        // stage2 B frags
__device__ __align__(16) uint2 d_Wgh[4*25*4*8*32];     // GRU B frags
__device__ float d_xa[128], d_xg[128], d_b2d[128];
__device__ __align__(16) uint32_t d_hph[NCELLS*128];   // new_h as half2 pairs
__device__ __align__(16) uint32_t d_nzh[NCELLS*128];   // noise as half2 pairs (defectors only)
__device__ float d_pfsum[NBLK*256];
__device__ float d_pexpout[NBLK*128];
__device__ float d_pexpsum[NBLK], d_ptsum[NBLK];
__device__ float d_SfP[2048*16], d_eorP[128*32], d_esP[64], d_tsP[64];
__device__ float d_fmean[8*256], d_go[256], d_gmean[256];

// ---------------- smem layout (u32 words) ----------------
#define HSW 132
#define OUW 76
#define S_HS 0
#define S_A2 8448          // [a1|g1] tile; reused as fp32 scratch after stage 2
#define S_OU 16896
#define S_T  21760
#define S_E  21824
#define S_PAY 21888
#define SMW  21952        // words -> 87808 bytes (2 CTAs/SM)

__device__ __forceinline__ uint32_t f2h2(float a, float b){
    __half2 h = __floats2half2_rn(a, b);
    return *reinterpret_cast<uint32_t*>(&h);
}
__device__ __forceinline__ float2 h2f2(uint32_t w){
    __half2 h = *reinterpret_cast<__half2*>(&w);
    return __half22float2(h);
}
__device__ __forceinline__ void mma16(float* c, const uint32_t* a, uint2 b){
    asm volatile(
        "mma.sync.aligned.m16n8k16.row.col.f32.f16.f16.f32 "
        "{%0,%1,%2,%3}, {%4,%5,%6,%7}, {%8,%9}, {%0,%1,%2,%3};"
        : "+f"(c[0]), "+f"(c[1]), "+f"(c[2]), "+f"(c[3])
        : "r"(a[0]), "r"(a[1]), "r"(a[2]), "r"(a[3]),
          "r"(b.x), "r"(b.y));
}
// fast gate math
__device__ __forceinline__ float fsig(float x){
    float e;
    asm("ex2.approx.ftz.f32 %0, %1;" : "=f"(e) : "f"(x * -1.4426950408889634f));
    float r;
    asm("rcp.approx.ftz.f32 %0, %1;" : "=f"(r) : "f"(1.0f + e));
    return r;
}
__device__ __forceinline__ float ftanh(float x){
    float r; asm("tanh.approx.f32 %0, %1;" : "=f"(r) : "f"(x)); return r;
}

// GRU weight value: K-map [out 0..127 | tension 128 | ones 129 | 0 | h 144..399]
__device__ __forceinline__ float gvv(int gate, int d, int k,
        const float* wih, const float* whh, const float* bih, const float* bhh){
    if (gate <= 1){
        int r = d + (gate==1 ? 256 : 0);
        if (k < 129) return wih[r*129+k];
        if (k == 129) return bih[r]+bhh[r];
        if (k >= 144) return whh[r*256+k-144];
        return 0.f;
    } else if (gate == 2){
        int r = 512 + d;
        if (k < 129) return wih[r*129+k];
        if (k == 129) return bih[r];
        return 0.f;
    } else {
        int r = 512 + d;
        if (k == 129) return bhh[r];
        if (k >= 144) return whh[r*256+k-144];
        return 0.f;
    }
}

// ================= kPrep =================
__global__ void kPrep(const float* __restrict__ x,
                      const float* __restrict__ aw1, const float* __restrict__ ab1,
                      const float* __restrict__ gw1, const float* __restrict__ gb1,
                      const float* __restrict__ aw2, const float* __restrict__ ab2,
                      const float* __restrict__ gw2, const float* __restrict__ gb2,
                      const float* __restrict__ wih, const float* __restrict__ whh,
                      const float* __restrict__ bih, const float* __restrict__ bhh) {
    int tid = blockIdx.x*blockDim.x + threadIdx.x;
    int nth = gridDim.x*blockDim.x;
    for (int i = tid; i < 16*32*32; i += nth){
        int lane=i&31, nb=(i>>5)&31, ks=i>>10;
        int t4=lane&3, g=lane>>2;
        int n = nb*8+g;
        const float* w = (n<128)? aw1 : gw1;
        int j = n & 127;
        int k0 = ks*16 + t4*2;
        const float* r = w + j*384 + 128;
        uint2 v; v.x = f2h2(r[k0], r[k0+1]); v.y = f2h2(r[k0+8], r[k0+9]);
        d_W1h[i] = v;
    }
    for (int i = tid; i < 16*16*32; i += nth){
        int lane=i&31, nb=(i>>5)&15, ks=i>>9;
        int t4=lane&3, g=lane>>2;
        int n = nb*8+g;
        int k0 = ks*16 + t4*2;
        float vv[4];
        #pragma unroll
        for (int q = 0; q < 4; q++){
            int k = k0 + (q>>1)*8 + (q&1);
            vv[q] = (k<128)? aw2[n*128+k] : -gw2[n*128+k-128];
        }
        uint2 v; v.x = f2h2(vv[0], vv[1]); v.y = f2h2(vv[2], vv[3]);
        d_W2h[i] = v;
    }
    for (int i = tid; i < 4*25*4*8*32; i += nth){
        int lane=i&31, nb=(i>>5)&7, gate=(i>>8)&3, rest=i>>10;
        int ks = rest%25, s = rest/25;
        int t4=lane&3, g=lane>>2;
        int d = s*64 + nb*8 + g;
        int k0 = ks*16 + t4*2;
        uint2 v;
        v.x = f2h2(gvv(gate,d,k0,wih,whh,bih,bhh),   gvv(gate,d,k0+1,wih,whh,bih,bhh));
        v.y = f2h2(gvv(gate,d,k0+8,wih,whh,bih,bhh), gvv(gate,d,k0+9,wih,whh,bih,bhh));
        d_Wgh[i] = v;
    }
    if (tid < 128){
        d_b2d[tid] = ab2[tid] - gb2[tid];
        float s = ab1[tid];
        const float* w = aw1 + tid*384;
        for (int k = 0; k < 128; k++) s = fmaf(x[k], w[k], s);
        d_xa[tid] = s;
        s = gb1[tid];
        w = gw1 + tid*384;
        for (int k = 0; k < 128; k++) s = fmaf(x[k], w[k], s);
        d_xg[tid] = s;
    }
}

// ================= kA: fp16 tensor-core fused pipeline (occ 2) =================
__global__ __launch_bounds__(256,2)
void kA(const float* __restrict__ hiddens, const float* __restrict__ payoffs){
    extern __shared__ uint32_t smu[];
    float* smf = (float*)smu;
    const int t = threadIdx.x, b = blockIdx.x, cell0 = b*MC;
    const int warp = t>>5, lane = t&31, gid = lane>>2, tig = lane&3;

    for (int e = t; e < 64*64; e += 256){
        int row = e>>6, c4 = e&63;
        float4 v = ((const float4*)hiddens)[(size_t)(cell0+row)*64 + c4];
        smu[S_HS + row*HSW + c4*2]     = f2h2(v.x, v.y);
        smu[S_HS + row*HSW + c4*2 + 1] = f2h2(v.z, v.w);
    }
    if (t < 64) smf[S_PAY+t] = payoffs[cell0+t];
    __syncthreads();

    // ---------- stage 1 ----------
    #pragma unroll 1
    for (int pass = 0; pass < 2; pass++){
        float acc[2][4][4];
        #pragma unroll
        for (int nbI = 0; nbI < 2; nbI++){
            int nb = warp + (pass*2+nbI)*8;
            int n = nb*8 + 2*tig;
            const float* xv = (nb < 16) ? (d_xa + n) : (d_xg + n - 128);
            float i0 = xv[0], i1 = xv[1];
            #pragma unroll
            for (int mb = 0; mb < 4; mb++){
                acc[nbI][mb][0]=i0; acc[nbI][mb][1]=i1; acc[nbI][mb][2]=i0; acc[nbI][mb][3]=i1;
            }
        }
        uint2 bf[2];
        #pragma unroll
        for (int nbI = 0; nbI < 2; nbI++)
            bf[nbI] = __ldg(d_W1h + (warp + (pass*2+nbI)*8)*32 + lane);
        #pragma unroll
        for (int ks = 0; ks < 16; ks++){
            uint2 bn[2];
            if (ks < 15){
                #pragma unroll
                for (int nbI = 0; nbI < 2; nbI++)
                    bn[nbI] = __ldg(d_W1h + ((ks+1)*32 + warp + (pass*2+nbI)*8)*32 + lane);
            }
            uint32_t af[4][4];
            #pragma unroll
            for (int mb = 0; mb < 4; mb++){
                const uint32_t* ap = smu + S_HS + (mb*16+gid)*HSW + ks*8 + tig;
                af[mb][0]=ap[0]; af[mb][1]=ap[8*HSW]; af[mb][2]=ap[4]; af[mb][3]=ap[8*HSW+4];
            }
            #pragma unroll
            for (int nbI = 0; nbI < 2; nbI++)
                #pragma unroll
                for (int mb = 0; mb < 4; mb++) mma16(acc[nbI][mb], af[mb], bf[nbI]);
            bf[0]=bn[0]; bf[1]=bn[1];
        }
        #pragma unroll
        for (int nbI = 0; nbI < 2; nbI++){
            int wcol = (warp + (pass*2+nbI)*8)*4 + tig;
            #pragma unroll
            for (int mb = 0; mb < 4; mb++){
                int row = mb*16 + gid;
                smu[S_A2 + row*HSW + wcol] =
                    f2h2(fmaxf(acc[nbI][mb][0],0.f), fmaxf(acc[nbI][mb][1],0.f));
                smu[S_A2 + (row+8)*HSW + wcol] =
                    f2h2(fmaxf(acc[nbI][mb][2],0.f), fmaxf(acc[nbI][mb][3],0.f));
            }
        }
    }
    __syncthreads();

    // ---------- stage 2 ----------
    {
        float ac2[2][4][4];
        #pragma unroll
        for (int nbI = 0; nbI < 2; nbI++){
            int n = (warp + nbI*8)*8 + 2*tig;
            float i0 = d_b2d[n], i1 = d_b2d[n+1];
            #pragma unroll
            for (int mb = 0; mb < 4; mb++){
                ac2[nbI][mb][0]=i0; ac2[nbI][mb][1]=i1; ac2[nbI][mb][2]=i0; ac2[nbI][mb][3]=i1;
            }
        }
        uint2 bf[2];
        #pragma unroll
        for (int nbI = 0; nbI < 2; nbI++)
            bf[nbI] = __ldg(d_W2h + (warp + nbI*8)*32 + lane);
        #pragma unroll
        for (int ks = 0; ks < 16; ks++){
            uint2 bn[2];
            if (ks < 15){
                #pragma unroll
                for (int nbI = 0; nbI < 2; nbI++)
                    bn[nbI] = __ldg(d_W2h + ((ks+1)*16 + warp + nbI*8)*32 + lane);
            }
            uint32_t af[4][4];
            #pragma unroll
            for (int mb = 0; mb < 4; mb++){
                const uint32_t* ap = smu + S_A2 + (mb*16+gid)*HSW + ks*8 + tig;
                af[mb][0]=ap[0]; af[mb][1]=ap[8*HSW]; af[mb][2]=ap[4]; af[mb][3]=ap[8*HSW+4];
            }
            #pragma unroll
            for (int nbI = 0; nbI < 2; nbI++)
                #pragma unroll
                for (int mb = 0; mb < 4; mb++) mma16(ac2[nbI][mb], af[mb], bf[nbI]);
            bf[0]=bn[0]; bf[1]=bn[1];
        }
        #pragma unroll
        for (int nbI = 0; nbI < 2; nbI++){
            int wcol = (warp + nbI*8)*4 + tig;
            #pragma unroll
            for (int mb = 0; mb < 4; mb++){
                int row = mb*16 + gid;
                smu[S_OU + row*OUW + wcol]     = f2h2(ac2[nbI][mb][0], ac2[nbI][mb][1]);
                smu[S_OU + (row+8)*OUW + wcol] = f2h2(ac2[nbI][mb][2], ac2[nbI][mb][3]);
            }
        }
    }
    __syncthreads();

    // ---------- tension: 4 threads per cell + quad shuffle ----------
    {
        int cell = t >> 2, q = t & 3;
        const uint32_t* o = smu + S_OU + cell*OUW + q*16;
        float s2 = 0.f;
        #pragma unroll
        for (int j = 0; j < 16; j++){
            float2 v = h2f2(o[j]);
            s2 = fmaf(v.x, v.x, s2); s2 = fmaf(v.y, v.y, s2);
        }
        s2 += __shfl_xor_sync(0xffffffffu, s2, 1);
        s2 += __shfl_xor_sync(0xffffffffu, s2, 2);
        if (q == 0){
            s2 *= (1.0f/128.0f);
            smf[S_T+cell] = s2;
            smf[S_E+cell] = expf(s2);
            uint32_t* ow = smu + S_OU + cell*OUW;
            ow[64] = f2h2(s2, 1.0f);
            #pragma unroll
            for (int c = 65; c < 72; c++) ow[c] = 0u;
        }
    }
    __syncthreads();
    // ---------- pexpout: 2 threads per j, scratch in dead S_A2 ----------
    {
        int j = t >> 1, half = t & 1;
        int wj = j >> 1, hi = j & 1;
        float s2 = 0.f;
        #pragma unroll 8
        for (int c = half*32; c < half*32 + 32; c++){
            float2 v = h2f2(smu[S_OU + c*OUW + wj]);
            s2 = fmaf(smf[S_E+c], hi ? v.y : v.x, s2);
        }
        smf[S_A2 + t] = s2;
    }
    __syncthreads();
    if (t < 128){
        d_pexpout[b*128+t] = smf[S_A2 + t*2] + smf[S_A2 + t*2 + 1];
    } else if (t == 128){
        float s2 = 0.f; for (int c = 0; c < 64; c++) s2 += smf[S_E+c];
        d_pexpsum[b] = s2;
    } else if (t == 129){
        float s2 = 0.f; for (int c = 0; c < 64; c++) s2 += smf[S_T+c];
        d_ptsum[b] = s2;
    }

    // ---------- GRU: 4 slices, 1 nb per warp, fused 4 gates ----------
    #pragma unroll 1
    for (int s = 0; s < 4; s++){
        float aR[4][4]={}, aZ[4][4]={}, aI[4][4]={}, aH[4][4]={};
        const uint2* wg0 = d_Wgh + ((s*25*4 + 0)*8 + warp)*32 + lane;
        uint2 bR = __ldg(wg0);
        uint2 bZ = __ldg(wg0 + 256);
        uint2 bI = __ldg(wg0 + 512);
        uint32_t af[4][4];
        #pragma unroll
        for (int mb = 0; mb < 4; mb++){
            const uint32_t* ap = smu + S_OU + (mb*16+gid)*OUW + tig;
            af[mb][0]=ap[0]; af[mb][1]=ap[8*OUW]; af[mb][2]=ap[4]; af[mb][3]=ap[8*OUW+4];
        }
        #pragma unroll
        for (int ks = 0; ks <= 8; ks++){
            uint2 bRn, bZn, bIn; uint32_t afn[4][4];
            if (ks < 8){
                const uint2* wn = wg0 + (ks+1)*1024;
                bRn = __ldg(wn); bZn = __ldg(wn + 256); bIn = __ldg(wn + 512);
                #pragma unroll
                for (int mb = 0; mb < 4; mb++){
                    const uint32_t* ap = smu + S_OU + (mb*16+gid)*OUW + (ks+1)*8 + tig;
                    afn[mb][0]=ap[0]; afn[mb][1]=ap[8*OUW]; afn[mb][2]=ap[4]; afn[mb][3]=ap[8*OUW+4];
                }
            }
            #pragma unroll
            for (int mb = 0; mb < 4; mb++){
                mma16(aR[mb], af[mb], bR);
                mma16(aZ[mb], af[mb], bZ);
                mma16(aI[mb], af[mb], bI);
            }
            if (ks == 8){
                uint2 bH8 = __ldg(wg0 + 8*1024 + 768);
                #pragma unroll
                for (int mb = 0; mb < 4; mb++) mma16(aH[mb], af[mb], bH8);
            }
            bR=bRn; bZ=bZn; bI=bIn;
            #pragma unroll
            for (int mb = 0; mb < 4; mb++)
                #pragma unroll
                for (int e2 = 0; e2 < 4; e2++) af[mb][e2] = afn[mb][e2];
        }
        {
            const uint2* w9 = wg0 + 9*1024;
            bR = __ldg(w9); bZ = __ldg(w9 + 256);
        }
        uint2 bH = __ldg(wg0 + 9*1024 + 768);
        #pragma unroll
        for (int mb = 0; mb < 4; mb++){
            const uint32_t* ap = smu + S_HS + (mb*16+gid)*HSW + tig;
            af[mb][0]=ap[0]; af[mb][1]=ap[8*HSW]; af[mb][2]=ap[4]; af[mb][3]=ap[8*HSW+4];
        }
        #pragma unroll
        for (int ks = 9; ks <= 24; ks++){
            uint2 bRn, bZn, bHn; uint32_t afn[4][4];
            if (ks < 24){
                const uint2* wn = wg0 + (ks+1)*1024;
                bRn = __ldg(wn); bZn = __ldg(wn + 256); bHn = __ldg(wn + 768);
                #pragma unroll
                for (int mb = 0; mb < 4; mb++){
                    const uint32_t* ap = smu + S_HS + (mb*16+gid)*HSW + ((ks+1)*8-72) + tig;
                    afn[mb][0]=ap[0]; afn[mb][1]=ap[8*HSW]; afn[mb][2]=ap[4]; afn[mb][3]=ap[8*HSW+4];
                }
            }
            #pragma unroll
            for (int mb = 0; mb < 4; mb++){
                mma16(aR[mb], af[mb], bR);
                mma16(aZ[mb], af[mb], bZ);
                mma16(aH[mb], af[mb], bH);
            }
            bR=bRn; bZ=bZn; bH=bHn;
            #pragma unroll
            for (int mb = 0; mb < 4; mb++)
                #pragma unroll
                for (int e2 = 0; e2 < 4; e2++) af[mb][e2] = afn[mb][e2];
        }

        int d0 = s*64 + warp*8 + 2*tig;
        float cs0 = 0.f, cs1 = 0.f;
        #pragma unroll
        for (int mb = 0; mb < 4; mb++){
            #pragma unroll
            for (int hf = 0; hf < 2; hf++){
                int row = mb*16 + gid + hf*8;
                int cell = cell0 + row;
                float2 hh = h2f2(smu[S_HS + row*HSW + (d0>>1)]);
                float sc = fmaf(0.02f, smf[S_PAY+row], 0.9f);
                float v0, v1;
                {
                    int e = hf*2;
                    float r  = fsig(aR[mb][e]);
                    float z  = fsig(aZ[mb][e]);
                    float nn = ftanh(fmaf(r, aH[mb][e], aI[mb][e]));
                    v0 = ((1.0f - z)*nn + z*hh.x) * sc;
                    v0 = fminf(10.0f, fmaxf(-10.0f, v0));
                    r  = fsig(aR[mb][e+1]);
                    z  = fsig(aZ[mb][e+1]);
                    nn = ftanh(fmaf(r, aH[mb][e+1], aI[mb][e+1]));
                    v1 = ((1.0f - z)*nn + z*hh.y) * sc;
                    v1 = fminf(10.0f, fmaxf(-10.0f, v1));
                }
                d_hph[(size_t)cell*128 + (d0>>1)] = f2h2(v0, v1);
                cs0 += v0; cs1 += v1;
            }
        }
        cs0 += __shfl_xor_sync(0xffffffffu, cs0, 4);
        cs0 += __shfl_xor_sync(0xffffffffu, cs0, 8);
        cs0 += __shfl_xor_sync(0xffffffffu, cs0, 16);
        cs1 += __shfl_xor_sync(0xffffffffu, cs1, 4);
        cs1 += __shfl_xor_sync(0xffffffffu, cs1, 8);
        cs1 += __shfl_xor_sync(0xffffffffu, cs1, 16);
        if (gid == 0){
            d_pfsum[b*256 + d0]     = cs0;
            d_pfsum[b*256 + d0 + 1] = cs1;
        }
    }
}

// ================= threefry (partitionable) + XLA erf_inv =================
__device__ __forceinline__ uint32_t threefry_bits(uint32_t x0, uint32_t x1) {
    const uint32_t ks0 = 0u, ks1 = 42u, ks2 = 0x1BD11BF0u;
    x0 += ks0; x1 += ks1;
#define RND(R) { x0 += x1; x1 = (x1 << R) | (x1 >> (32 - R)); x1 ^= x0; }
    RND(13) RND(15) RND(26) RND(6)   x0 += ks1; x1 += ks2 + 1u;
    RND(17) RND(29) RND(16) RND(24)  x0 += ks2; x1 += ks0 + 2u;
    RND(13) RND(15) RND(26) RND(6)   x0 += ks0; x1 += ks1 + 3u;
    RND(17) RND(29) RND(16) RND(24)  x0 += ks1; x1 += ks2 + 4u;
    RND(13) RND(15) RND(26) RND(6)   x0 += ks2; x1 += ks0 + 5u;
#undef RND
    return x0 ^ x1;
}
__device__ __forceinline__ float erfinv_xla(float x) {
    float w = -__logf(fmaf(-x, x, 1.0f));
    float p;
    if (w < 5.0f){
        w -= 2.5f;
        p = 2.81022636e-08f;
        p = fmaf(p, w, 3.43273939e-07f);  p = fmaf(p, w, -3.5233877e-06f);
        p = fmaf(p, w, -4.39150654e-06f); p = fmaf(p, w, 0.00021858087f);
        p = fmaf(p, w, -0.00125372503f);  p = fmaf(p, w, -0.00417768164f);
        p = fmaf(p, w, 0.246640727f);     p = fmaf(p, w, 1.50140941f);
    } else {
        w = sqrtf(w) - 3.0f;
        p = -0.000200214257f;
        p = fmaf(p, w, 0.000100950558f);  p = fmaf(p, w, 0.00134934322f);
        p = fmaf(p, w, -0.00367342844f);  p = fmaf(p, w, 0.00573950773f);
        p = fmaf(p, w, -0.0076224613f);   p = fmaf(p, w, 0.00943887047f);
        p = fmaf(p, w, 1.00167406f);      p = fmaf(p, w, 2.83297682f);
    }
    return p*x;
}
__device__ __forceinline__ float bits_to_normal(uint32_t bits) {
    float u01 = __uint_as_float((bits >> 9) | 0x3f800000u) - 1.0f;
    float u = u01*2.0f + (-0.99999994f);
    u = fmaxf(-0.99999994f, u);
    return 1.4142135623730951f*erfinv_xla(u);
}

// ================= kNoise: defector cells only; fork stream =================
__global__ __launch_bounds__(128)
void kNoise(const int* __restrict__ lact){
    const int cell = blockIdx.x;
    const int dp = threadIdx.x;
    const int l0 = lact[cell];
    const int l1 = lact[cell + 65536];
    uint32_t m = (uint32_t)cell*256u + (uint32_t)(dp*2);
    if (!l0){
        float a = 0.02f*bits_to_normal(threefry_bits(0u, m));
        float bq = 0.02f*bits_to_normal(threefry_bits(0u, m + 1u));
        d_nzh[(size_t)cell*128 + dp] = f2h2(a, bq);
    }
    if (!l1){
        float a = 0.02f*bits_to_normal(threefry_bits(0u, m + 16777216u));
        float bq = 0.02f*bits_to_normal(threefry_bits(0u, m + 16777217u));
        d_nzh[(size_t)(cell+65536)*128 + dp] = f2h2(a, bq);
    }
}

// ================= kB1a: coalesced partial reductions (wide) =================
__global__ void kB1a() {
    const int b = blockIdx.x, t = threadIdx.x;
    if (b < 128){
        int f = b >> 4, c = b & 15;
        const float* p = d_pfsum + (size_t)(f*256 + c*16)*256 + t;
        float S = 0.f;
        #pragma unroll
        for (int i = 0; i < 16; i++) S += p[(size_t)i*256];
        d_SfP[(f*256 + t)*16 + c] = S;
    } else if (b < 160){
        if (t < 128){
            int c = b - 128;
            const float* p = d_pexpout + (size_t)(c*64)*128 + t;
            float s = 0.f;
            #pragma unroll 8
            for (int i = 0; i < 64; i++) s += p[(size_t)i*128];
            d_eorP[t*32 + c] = s;
        }
    } else {
        if (t < 64){
            float s = 0.f;
            #pragma unroll 8
            for (int i = 0; i < 32; i++) s += d_pexpsum[t*32+i];
            d_esP[t] = s;
        } else if (t < 128){
            int c = t - 64; float s = 0.f;
            #pragma unroll 8
            for (int i = 0; i < 32; i++) s += d_ptsum[c*32+i];
            d_tsP[c] = s;
        }
    }
}

// ================= kB2m: merged combine + stats + pred (single block) =================
__global__ __launch_bounds__(1024,1)
void kB2m(const float* __restrict__ head_w, const float* __restrict__ head_b,
          const int* __restrict__ stepp, float* __restrict__ out) {
    __shared__ float sSf[2048], sDf[2048], sEor[128], sEs, sTs;
    const int t = threadIdx.x;
    const int step = *stepp;

    for (int i = t; i < 2048; i += 1024){
        const float* p = d_SfP + i*16;
        float S = 0.f;
        #pragma unroll
        for (int c = 0; c < 16; c++) S += p[c];
        sSf[i] = S;
        sDf[i] = p[0] + p[1] + p[2] + p[3];
    }
    if (t < 128){
        const float* p = d_eorP + t*32;
        float s = 0.f;
        #pragma unroll
        for (int c = 0; c < 32; c++) s += p[c];
        sEor[t] = s;
    } else if (t == 128){
        float s = 0.f;
        #pragma unroll
        for (int c = 0; c < 64; c++) s += d_esP[c];
        sEs = s;
    } else if (t == 129){
        float s = 0.f;
        #pragma unroll
        for (int c = 0; c < 64; c++) s += d_tsP[c];
        sTs = s;
    }
    __syncthreads();

    if (t < 256){
        float Sfv[8];
        #pragma unroll
        for (int f = 0; f < 8; f++) Sfv[f] = sSf[f*256+t];
        float go = 0.f;
        #pragma unroll
        for (int f = 0; f < 8; f++) go += Sfv[f]*(1.0f/16384.0f);
        go *= 0.125f;
        d_go[t] = go;
        float gsum = 0.f;
        #pragma unroll
        for (int f = 0; f < 8; f++){
            float fm = Sfv[f]*(1.0f/16384.0f);
            d_fmean[f*256+t] = fm;
            float Tf = Sfv[f];
            if (step > 5){
                float D = sDf[f*256+t];
                Tf += 0.15f*(4096.0f*go - 0.85f*D - 4096.0f*0.15f*fm);
            }
            gsum += Tf;
        }
        d_gmean[t] = gsum*(1.0f/131072.0f);
    } else if (t >= 256 && t < 384){
        int j = t - 256;
        float inv = 1.0f/sEs;
        float s = head_b[j];
        const float* hw = head_w + j*128;
        for (int k = 0; k < 128; k++) s = fmaf(sEor[k]*inv, hw[k], s);
        out[j] = s;
    } else if (t == 384){
        out[128] = sTs*(1.0f/131072.0f);
    }
}

// ================= kC2: sync/debate/pull + noise(defectors) + clamp =================
__global__ __launch_bounds__(128)
void kC2(const int* __restrict__ lact, const int* __restrict__ stepp,
         float* __restrict__ out) {
    const int cell = blockIdx.x;
    const int dp = threadIdx.x;
    const int step = *stepp;
    const float gm0 = d_gmean[dp*2],  gm1 = d_gmean[dp*2+1];
    const float go0 = d_go[dp*2],     go1 = d_go[dp*2+1];
    #pragma unroll
    for (int half = 0; half < 2; half++){
        int c = cell + half*65536;
        int la = lact[c];
        float coop = (float)la;
        int f = c >> 14;
        float2 hp = h2f2(d_hph[(size_t)c*128 + dp]);
        float2 nz = make_float2(0.f, 0.f);
        if (la == 0) nz = h2f2(d_nzh[(size_t)c*128 + dp]);
        float fm0 = d_fmean[f*256 + dp*2], fm1 = d_fmean[f*256 + dp*2 + 1];
        float v0 = 0.85f*hp.x + 0.15f*fm0;
        float v1 = 0.85f*hp.y + 0.15f*fm1;
        if (step > 5 && (c & 16383) < DC){
            v0 = 0.85f*v0 + 0.15f*go0;
            v1 = 0.85f*v1 + 0.15f*go1;
        }
        v0 += 0.05f*coop*(gm0 - v0);
        v1 += 0.05f*coop*(gm1 - v1);
        v0 += nz.x; v1 += nz.y;
        v0 = fminf(10.0f, fmaxf(-10.0f, v0));
        v1 = fminf(10.0f, fmaxf(-10.0f, v1));
        out[129 + (size_t)c*256 + dp*2]     = v0;
        out[129 + (size_t)c*256 + dp*2 + 1] = v1;
    }
}

// ================= launch (fork kNoise onto a second captured stream) =================
extern "C" void kernel_launch(void* const* d_in, const int* in_sizes, int n_in,
                              void* d_out, int out_size) {
    const float* x       = (const float*)d_in[0];
    const float* payoffs = (const float*)d_in[1];
    const int*   last    = (const int*)d_in[2];
    const int*   step    = (const int*)d_in[3];
    const float* hiddens = (const float*)d_in[4];
    const float* a_w1    = (const float*)d_in[5];
    const float* a_b1    = (const float*)d_in[6];
    const float* a_w2    = (const float*)d_in[7];
    const float* a_b2    = (const float*)d_in[8];
    const float* g_w1    = (const float*)d_in[9];
    const float* g_b1    = (const float*)d_in[10];
    const float* g_w2    = (const float*)d_in[11];
    const float* g_b2    = (const float*)d_in[12];
    const float* gru_wih = (const float*)d_in[13];
    const float* gru_whh = (const float*)d_in[14];
    const float* gru_bih = (const float*)d_in[15];
    const float* gru_bhh = (const float*)d_in[16];
    const float* head_w  = (const float*)d_in[17];
    const float* head_b  = (const float*)d_in[18];
    float* out = (float*)d_out;

    cudaFuncSetAttribute(kA, cudaFuncAttributeMaxDynamicSharedMemorySize, SMW*4);

    cudaStream_t s2;
    cudaEvent_t ev0, ev1;
    cudaStreamCreate(&s2);
    cudaEventCreateWithFlags(&ev0, cudaEventDisableTiming);
    cudaEventCreateWithFlags(&ev1, cudaEventDisableTiming);

    // fork: noise generation depends only on last_action
    cudaEventRecord(ev0, 0);
    cudaStreamWaitEvent(s2, ev0, 0);
    kNoise<<<65536, 128, 0, s2>>>(last);
    cudaEventRecord(ev1, s2);

    // main chain
    kPrep<<<1024, 256>>>(x, a_w1, a_b1, g_w1, g_b1, a_w2, a_b2, g_w2, g_b2,
                         gru_wih, gru_whh, gru_bih, gru_bhh);
    kA<<<NBLK, 256, SMW*4>>>(hiddens, payoffs);
    kB1a<<<161, 256>>>();
    kB2m<<<1, 1024>>>(head_w, head_b, step, out);

    // join: kC2 needs both stats and noise
    cudaStreamWaitEvent(0, ev1, 0);
    kC2<<<65536, 128>>>(last, step, out);
}

// round 17
// speedup vs baseline: 1.0091x; 1.0091x over previous
#include <cuda_runtime.h>
#include <cuda_fp16.h>
#include <cstdint>

#define NCELLS 131072
#define MC     64
#define NBLK   (NCELLS/MC)   // 2048
#define DC     4096

// ---------------- device scratch ----------------
__device__ __align__(16) uint2 d_W1h[16*32*32];        // stage1 B frags (fp16)
__device__ __align__(16) uint2 d_W2h[16*16*32];        // stage2 B frags
__device__ __align__(16) uint2 d_Wgh[4*25*4*8*32];     // GRU B frags
__device__ float d_xa[128], d_xg[128], d_b2d[128];
__device__ __align__(16) uint32_t d_hph[NCELLS*128];   // new_h as half2 pairs
__device__ __align__(16) uint32_t d_nzh[NCELLS*128];   // noise as half2 pairs (defectors only)
__device__ float d_pfsum[NBLK*256];
__device__ float d_pexpout[NBLK*128];
__device__ float d_pexpsum[NBLK], d_ptsum[NBLK];
__device__ float d_SfP[2048*16], d_eorP[128*32], d_esP[64], d_tsP[64];
__device__ float d_fmean[8*256], d_go[256], d_gmean[256];

// ---------------- smem layout (u32 words) ----------------
#define HSW 132
#define OUW 76
#define S_HS 0
#define S_A2 8448          // [a1|g1] tile; reused as fp32 scratch after stage 2
#define S_OU 16896
#define S_T  21760
#define S_E  21824
#define S_PAY 21888
#define SMW  21952        // words -> 87808 bytes (2 CTAs/SM)

__device__ __forceinline__ uint32_t f2h2(float a, float b){
    __half2 h = __floats2half2_rn(a, b);
    return *reinterpret_cast<uint32_t*>(&h);
}
__device__ __forceinline__ float2 h2f2(uint32_t w){
    __half2 h = *reinterpret_cast<__half2*>(&w);
    return __half22float2(h);
}
__device__ __forceinline__ void mma16(float* c, const uint32_t* a, uint2 b){
    asm volatile(
        "mma.sync.aligned.m16n8k16.row.col.f32.f16.f16.f32 "
        "{%0,%1,%2,%3}, {%4,%5,%6,%7}, {%8,%9}, {%0,%1,%2,%3};"
        : "+f"(c[0]), "+f"(c[1]), "+f"(c[2]), "+f"(c[3])
        : "r"(a[0]), "r"(a[1]), "r"(a[2]), "r"(a[3]),
          "r"(b.x), "r"(b.y));
}
// ldmatrix x4: loads full m16k16 fp16 A fragment (r0..r3 = a0..a3)
__device__ __forceinline__ void ldsm4(uint32_t* r, uint32_t saddr){
    asm volatile("ldmatrix.sync.aligned.m8n8.x4.shared.b16 {%0,%1,%2,%3}, [%4];"
        : "=r"(r[0]), "=r"(r[1]), "=r"(r[2]), "=r"(r[3]) : "r"(saddr));
}
// fast gate math
__device__ __forceinline__ float fsig(float x){
    float e;
    asm("ex2.approx.ftz.f32 %0, %1;" : "=f"(e) : "f"(x * -1.4426950408889634f));
    float r;
    asm("rcp.approx.ftz.f32 %0, %1;" : "=f"(r) : "f"(1.0f + e));
    return r;
}
__device__ __forceinline__ float ftanh(float x){
    float r; asm("tanh.approx.f32 %0, %1;" : "=f"(r) : "f"(x)); return r;
}

// GRU weight value: K-map [out 0..127 | tension 128 | ones 129 | 0 | h 144..399]
__device__ __forceinline__ float gvv(int gate, int d, int k,
        const float* wih, const float* whh, const float* bih, const float* bhh){
    if (gate <= 1){
        int r = d + (gate==1 ? 256 : 0);
        if (k < 129) return wih[r*129+k];
        if (k == 129) return bih[r]+bhh[r];
        if (k >= 144) return whh[r*256+k-144];
        return 0.f;
    } else if (gate == 2){
        int r = 512 + d;
        if (k < 129) return wih[r*129+k];
        if (k == 129) return bih[r];
        return 0.f;
    } else {
        int r = 512 + d;
        if (k == 129) return bhh[r];
        if (k >= 144) return whh[r*256+k-144];
        return 0.f;
    }
}

// ================= kPrep =================
__global__ void kPrep(const float* __restrict__ x,
                      const float* __restrict__ aw1, const float* __restrict__ ab1,
                      const float* __restrict__ gw1, const float* __restrict__ gb1,
                      const float* __restrict__ aw2, const float* __restrict__ ab2,
                      const float* __restrict__ gw2, const float* __restrict__ gb2,
                      const float* __restrict__ wih, const float* __restrict__ whh,
                      const float* __restrict__ bih, const float* __restrict__ bhh) {
    int tid = blockIdx.x*blockDim.x + threadIdx.x;
    int nth = gridDim.x*blockDim.x;
    for (int i = tid; i < 16*32*32; i += nth){
        int lane=i&31, nb=(i>>5)&31, ks=i>>10;
        int t4=lane&3, g=lane>>2;
        int n = nb*8+g;
        const float* w = (n<128)? aw1 : gw1;
        int j = n & 127;
        int k0 = ks*16 + t4*2;
        const float* r = w + j*384 + 128;
        uint2 v; v.x = f2h2(r[k0], r[k0+1]); v.y = f2h2(r[k0+8], r[k0+9]);
        d_W1h[i] = v;
    }
    for (int i = tid; i < 16*16*32; i += nth){
        int lane=i&31, nb=(i>>5)&15, ks=i>>9;
        int t4=lane&3, g=lane>>2;
        int n = nb*8+g;
        int k0 = ks*16 + t4*2;
        float vv[4];
        #pragma unroll
        for (int q = 0; q < 4; q++){
            int k = k0 + (q>>1)*8 + (q&1);
            vv[q] = (k<128)? aw2[n*128+k] : -gw2[n*128+k-128];
        }
        uint2 v; v.x = f2h2(vv[0], vv[1]); v.y = f2h2(vv[2], vv[3]);
        d_W2h[i] = v;
    }
    for (int i = tid; i < 4*25*4*8*32; i += nth){
        int lane=i&31, nb=(i>>5)&7, gate=(i>>8)&3, rest=i>>10;
        int ks = rest%25, s = rest/25;
        int t4=lane&3, g=lane>>2;
        int d = s*64 + nb*8 + g;
        int k0 = ks*16 + t4*2;
        uint2 v;
        v.x = f2h2(gvv(gate,d,k0,wih,whh,bih,bhh),   gvv(gate,d,k0+1,wih,whh,bih,bhh));
        v.y = f2h2(gvv(gate,d,k0+8,wih,whh,bih,bhh), gvv(gate,d,k0+9,wih,whh,bih,bhh));
        d_Wgh[i] = v;
    }
    if (tid < 128){
        d_b2d[tid] = ab2[tid] - gb2[tid];
        float s = ab1[tid];
        const float* w = aw1 + tid*384;
        for (int k = 0; k < 128; k++) s = fmaf(x[k], w[k], s);
        d_xa[tid] = s;
        s = gb1[tid];
        w = gw1 + tid*384;
        for (int k = 0; k < 128; k++) s = fmaf(x[k], w[k], s);
        d_xg[tid] = s;
    }
}

// ================= kA: fp16 tensor-core fused pipeline (occ 2, LDSM A-frags) =================
__global__ __launch_bounds__(256,2)
void kA(const float* __restrict__ hiddens, const float* __restrict__ payoffs){
    extern __shared__ uint32_t smu[];
    float* smf = (float*)smu;
    const int t = threadIdx.x, b = blockIdx.x, cell0 = b*MC;
    const int warp = t>>5, lane = t&31, gid = lane>>2, tig = lane&3;

    // per-thread ldmatrix base offsets (bytes)
    const uint32_t smb = (uint32_t)__cvta_generic_to_shared(smu);
    const int rowoff = (lane & 7) + ((lane >> 3) & 1)*8;   // row within 16-row frag
    const int khalf  = (lane >> 4) * 8;                     // col offset (halfs)
    const uint32_t offH  = smb + S_HS*4 + (uint32_t)rowoff*(HSW*4) + khalf*2;
    const uint32_t offA2 = smb + S_A2*4 + (uint32_t)rowoff*(HSW*4) + khalf*2;
    const uint32_t offOU = smb + S_OU*4 + (uint32_t)rowoff*(OUW*4) + khalf*2;

    for (int e = t; e < 64*64; e += 256){
        int row = e>>6, c4 = e&63;
        float4 v = ((const float4*)hiddens)[(size_t)(cell0+row)*64 + c4];
        smu[S_HS + row*HSW + c4*2]     = f2h2(v.x, v.y);
        smu[S_HS + row*HSW + c4*2 + 1] = f2h2(v.z, v.w);
    }
    if (t < 64) smf[S_PAY+t] = payoffs[cell0+t];
    __syncthreads();

    // ---------- stage 1 ----------
    #pragma unroll 1
    for (int pass = 0; pass < 2; pass++){
        float acc[2][4][4];
        #pragma unroll
        for (int nbI = 0; nbI < 2; nbI++){
            int nb = warp + (pass*2+nbI)*8;
            int n = nb*8 + 2*tig;
            const float* xv = (nb < 16) ? (d_xa + n) : (d_xg + n - 128);
            float i0 = xv[0], i1 = xv[1];
            #pragma unroll
            for (int mb = 0; mb < 4; mb++){
                acc[nbI][mb][0]=i0; acc[nbI][mb][1]=i1; acc[nbI][mb][2]=i0; acc[nbI][mb][3]=i1;
            }
        }
        uint2 bf[2];
        #pragma unroll
        for (int nbI = 0; nbI < 2; nbI++)
            bf[nbI] = __ldg(d_W1h + (warp + (pass*2+nbI)*8)*32 + lane);
        #pragma unroll
        for (int ks = 0; ks < 16; ks++){
            uint2 bn[2];
            if (ks < 15){
                #pragma unroll
                for (int nbI = 0; nbI < 2; nbI++)
                    bn[nbI] = __ldg(d_W1h + ((ks+1)*32 + warp + (pass*2+nbI)*8)*32 + lane);
            }
            uint32_t af[4][4];
            #pragma unroll
            for (int mb = 0; mb < 4; mb++)
                ldsm4(af[mb], offH + (uint32_t)(mb*16*(HSW*4) + ks*32));
            #pragma unroll
            for (int nbI = 0; nbI < 2; nbI++)
                #pragma unroll
                for (int mb = 0; mb < 4; mb++) mma16(acc[nbI][mb], af[mb], bf[nbI]);
            bf[0]=bn[0]; bf[1]=bn[1];
        }
        #pragma unroll
        for (int nbI = 0; nbI < 2; nbI++){
            int wcol = (warp + (pass*2+nbI)*8)*4 + tig;
            #pragma unroll
            for (int mb = 0; mb < 4; mb++){
                int row = mb*16 + gid;
                smu[S_A2 + row*HSW + wcol] =
                    f2h2(fmaxf(acc[nbI][mb][0],0.f), fmaxf(acc[nbI][mb][1],0.f));
                smu[S_A2 + (row+8)*HSW + wcol] =
                    f2h2(fmaxf(acc[nbI][mb][2],0.f), fmaxf(acc[nbI][mb][3],0.f));
            }
        }
        __syncthreads();
    }

    // ---------- stage 2 ----------
    {
        float ac2[2][4][4];
        #pragma unroll
        for (int nbI = 0; nbI < 2; nbI++){
            int n = (warp + nbI*8)*8 + 2*tig;
            float i0 = d_b2d[n], i1 = d_b2d[n+1];
            #pragma unroll
            for (int mb = 0; mb < 4; mb++){
                ac2[nbI][mb][0]=i0; ac2[nbI][mb][1]=i1; ac2[nbI][mb][2]=i0; ac2[nbI][mb][3]=i1;
            }
        }
        uint2 bf[2];
        #pragma unroll
        for (int nbI = 0; nbI < 2; nbI++)
            bf[nbI] = __ldg(d_W2h + (warp + nbI*8)*32 + lane);
        #pragma unroll
        for (int ks = 0; ks < 16; ks++){
            uint2 bn[2];
            if (ks < 15){
                #pragma unroll
                for (int nbI = 0; nbI < 2; nbI++)
                    bn[nbI] = __ldg(d_W2h + ((ks+1)*16 + warp + nbI*8)*32 + lane);
            }
            uint32_t af[4][4];
            #pragma unroll
            for (int mb = 0; mb < 4; mb++)
                ldsm4(af[mb], offA2 + (uint32_t)(mb*16*(HSW*4) + ks*32));
            #pragma unroll
            for (int nbI = 0; nbI < 2; nbI++)
                #pragma unroll
                for (int mb = 0; mb < 4; mb++) mma16(ac2[nbI][mb], af[mb], bf[nbI]);
            bf[0]=bn[0]; bf[1]=bn[1];
        }
        #pragma unroll
        for (int nbI = 0; nbI < 2; nbI++){
            int wcol = (warp + nbI*8)*4 + tig;
            #pragma unroll
            for (int mb = 0; mb < 4; mb++){
                int row = mb*16 + gid;
                smu[S_OU + row*OUW + wcol]     = f2h2(ac2[nbI][mb][0], ac2[nbI][mb][1]);
                smu[S_OU + (row+8)*OUW + wcol] = f2h2(ac2[nbI][mb][2], ac2[nbI][mb][3]);
            }
        }
    }
    __syncthreads();

    // ---------- tension: 4 threads per cell + quad shuffle ----------
    {
        int cell = t >> 2, q = t & 3;
        const uint32_t* o = smu + S_OU + cell*OUW + q*16;
        float s2 = 0.f;
        #pragma unroll
        for (int j = 0; j < 16; j++){
            float2 v = h2f2(o[j]);
            s2 = fmaf(v.x, v.x, s2); s2 = fmaf(v.y, v.y, s2);
        }
        s2 += __shfl_xor_sync(0xffffffffu, s2, 1);
        s2 += __shfl_xor_sync(0xffffffffu, s2, 2);
        if (q == 0){
            s2 *= (1.0f/128.0f);
            smf[S_T+cell] = s2;
            smf[S_E+cell] = expf(s2);
            uint32_t* ow = smu + S_OU + cell*OUW;
            ow[64] = f2h2(s2, 1.0f);
            #pragma unroll
            for (int c = 65; c < 72; c++) ow[c] = 0u;
        }
    }
    __syncthreads();
    // ---------- pexpout: 2 threads per j, scratch in dead S_A2 ----------
    {
        int j = t >> 1, half = t & 1;
        int wj = j >> 1, hi = j & 1;
        float s2 = 0.f;
        #pragma unroll 8
        for (int c = half*32; c < half*32 + 32; c++){
            float2 v = h2f2(smu[S_OU + c*OUW + wj]);
            s2 = fmaf(smf[S_E+c], hi ? v.y : v.x, s2);
        }
        smf[S_A2 + t] = s2;
    }
    __syncthreads();
    if (t < 128){
        d_pexpout[b*128+t] = smf[S_A2 + t*2] + smf[S_A2 + t*2 + 1];
    } else if (t == 128){
        float s2 = 0.f; for (int c = 0; c < 64; c++) s2 += smf[S_E+c];
        d_pexpsum[b] = s2;
    } else if (t == 129){
        float s2 = 0.f; for (int c = 0; c < 64; c++) s2 += smf[S_T+c];
        d_ptsum[b] = s2;
    }

    // ---------- GRU: 4 slices, 1 nb per warp, fused 4 gates ----------
    #pragma unroll 1
    for (int s = 0; s < 4; s++){
        float aR[4][4]={}, aZ[4][4]={}, aI[4][4]={}, aH[4][4]={};
        const uint2* wg0 = d_Wgh + ((s*25*4 + 0)*8 + warp)*32 + lane;
        uint2 bR = __ldg(wg0);
        uint2 bZ = __ldg(wg0 + 256);
        uint2 bI = __ldg(wg0 + 512);
        uint32_t af[4][4];
        #pragma unroll
        for (int mb = 0; mb < 4; mb++)
            ldsm4(af[mb], offOU + (uint32_t)(mb*16*(OUW*4)));
        #pragma unroll
        for (int ks = 0; ks <= 8; ks++){
            uint2 bRn, bZn, bIn; uint32_t afn[4][4];
            if (ks < 8){
                const uint2* wn = wg0 + (ks+1)*1024;
                bRn = __ldg(wn); bZn = __ldg(wn + 256); bIn = __ldg(wn + 512);
                #pragma unroll
                for (int mb = 0; mb < 4; mb++)
                    ldsm4(afn[mb], offOU + (uint32_t)(mb*16*(OUW*4) + (ks+1)*32));
            }
            #pragma unroll
            for (int mb = 0; mb < 4; mb++){
                mma16(aR[mb], af[mb], bR);
                mma16(aZ[mb], af[mb], bZ);
                mma16(aI[mb], af[mb], bI);
            }
            if (ks == 8){
                uint2 bH8 = __ldg(wg0 + 8*1024 + 768);
                #pragma unroll
                for (int mb = 0; mb < 4; mb++) mma16(aH[mb], af[mb], bH8);
            }
            bR=bRn; bZ=bZn; bI=bIn;
            #pragma unroll
            for (int mb = 0; mb < 4; mb++)
                #pragma unroll
                for (int e2 = 0; e2 < 4; e2++) af[mb][e2] = afn[mb][e2];
        }
        {
            const uint2* w9 = wg0 + 9*1024;
            bR = __ldg(w9); bZ = __ldg(w9 + 256);
        }
        uint2 bH = __ldg(wg0 + 9*1024 + 768);
        #pragma unroll
        for (int mb = 0; mb < 4; mb++)
            ldsm4(af[mb], offH + (uint32_t)(mb*16*(HSW*4)));   // ks=9 -> h col 0
        #pragma unroll
        for (int ks = 9; ks <= 24; ks++){
            uint2 bRn, bZn, bHn; uint32_t afn[4][4];
            if (ks < 24){
                const uint2* wn = wg0 + (ks+1)*1024;
                bRn = __ldg(wn); bZn = __ldg(wn + 256); bHn = __ldg(wn + 768);
                #pragma unroll
                for (int mb = 0; mb < 4; mb++)
                    ldsm4(afn[mb], offH + (uint32_t)(mb*16*(HSW*4) + (ks+1)*32 - 288));
            }
            #pragma unroll
            for (int mb = 0; mb < 4; mb++){
                mma16(aR[mb], af[mb], bR);
                mma16(aZ[mb], af[mb], bZ);
                mma16(aH[mb], af[mb], bH);
            }
            bR=bRn; bZ=bZn; bH=bHn;
            #pragma unroll
            for (int mb = 0; mb < 4; mb++)
                #pragma unroll
                for (int e2 = 0; e2 < 4; e2++) af[mb][e2] = afn[mb][e2];
        }

        int d0 = s*64 + warp*8 + 2*tig;
        float cs0 = 0.f, cs1 = 0.f;
        #pragma unroll
        for (int mb = 0; mb < 4; mb++){
            #pragma unroll
            for (int hf = 0; hf < 2; hf++){
                int row = mb*16 + gid + hf*8;
                int cell = cell0 + row;
                float2 hh = h2f2(smu[S_HS + row*HSW + (d0>>1)]);
                float sc = fmaf(0.02f, smf[S_PAY+row], 0.9f);
                float v0, v1;
                {
                    int e = hf*2;
                    float r  = fsig(aR[mb][e]);
                    float z  = fsig(aZ[mb][e]);
                    float nn = ftanh(fmaf(r, aH[mb][e], aI[mb][e]));
                    v0 = ((1.0f - z)*nn + z*hh.x) * sc;
                    v0 = fminf(10.0f, fmaxf(-10.0f, v0));
                    r  = fsig(aR[mb][e+1]);
                    z  = fsig(aZ[mb][e+1]);
                    nn = ftanh(fmaf(r, aH[mb][e+1], aI[mb][e+1]));
                    v1 = ((1.0f - z)*nn + z*hh.y) * sc;
                    v1 = fminf(10.0f, fmaxf(-10.0f, v1));
                }
                d_hph[(size_t)cell*128 + (d0>>1)] = f2h2(v0, v1);
                cs0 += v0; cs1 += v1;
            }
        }
        cs0 += __shfl_xor_sync(0xffffffffu, cs0, 4);
        cs0 += __shfl_xor_sync(0xffffffffu, cs0, 8);
        cs0 += __shfl_xor_sync(0xffffffffu, cs0, 16);
        cs1 += __shfl_xor_sync(0xffffffffu, cs1, 4);
        cs1 += __shfl_xor_sync(0xffffffffu, cs1, 8);
        cs1 += __shfl_xor_sync(0xffffffffu, cs1, 16);
        if (gid == 0){
            d_pfsum[b*256 + d0]     = cs0;
            d_pfsum[b*256 + d0 + 1] = cs1;
        }
    }
}

// ================= threefry (partitionable) + XLA erf_inv =================
__device__ __forceinline__ uint32_t threefry_bits(uint32_t x0, uint32_t x1) {
    const uint32_t ks0 = 0u, ks1 = 42u, ks2 = 0x1BD11BF0u;
    x0 += ks0; x1 += ks1;
#define RND(R) { x0 += x1; x1 = (x1 << R) | (x1 >> (32 - R)); x1 ^= x0; }
    RND(13) RND(15) RND(26) RND(6)   x0 += ks1; x1 += ks2 + 1u;
    RND(17) RND(29) RND(16) RND(24)  x0 += ks2; x1 += ks0 + 2u;
    RND(13) RND(15) RND(26) RND(6)   x0 += ks0; x1 += ks1 + 3u;
    RND(17) RND(29) RND(16) RND(24)  x0 += ks1; x1 += ks2 + 4u;
    RND(13) RND(15) RND(26) RND(6)   x0 += ks2; x1 += ks0 + 5u;
#undef RND
    return x0 ^ x1;
}
__device__ __forceinline__ float erfinv_xla(float x) {
    float w = -__logf(fmaf(-x, x, 1.0f));
    float p;
    if (w < 5.0f){
        w -= 2.5f;
        p = 2.81022636e-08f;
        p = fmaf(p, w, 3.43273939e-07f);  p = fmaf(p, w, -3.5233877e-06f);
        p = fmaf(p, w, -4.39150654e-06f); p = fmaf(p, w, 0.00021858087f);
        p = fmaf(p, w, -0.00125372503f);  p = fmaf(p, w, -0.00417768164f);
        p = fmaf(p, w, 0.246640727f);     p = fmaf(p, w, 1.50140941f);
    } else {
        w = sqrtf(w) - 3.0f;
        p = -0.000200214257f;
        p = fmaf(p, w, 0.000100950558f);  p = fmaf(p, w, 0.00134934322f);
        p = fmaf(p, w, -0.00367342844f);  p = fmaf(p, w, 0.00573950773f);
        p = fmaf(p, w, -0.0076224613f);   p = fmaf(p, w, 0.00943887047f);
        p = fmaf(p, w, 1.00167406f);      p = fmaf(p, w, 2.83297682f);
    }
    return p*x;
}
__device__ __forceinline__ float bits_to_normal(uint32_t bits) {
    float u01 = __uint_as_float((bits >> 9) | 0x3f800000u) - 1.0f;
    float u = u01*2.0f + (-0.99999994f);
    u = fmaxf(-0.99999994f, u);
    return 1.4142135623730951f*erfinv_xla(u);
}

// ================= kNoise: defector cells only; fork stream =================
__global__ __launch_bounds__(128)
void kNoise(const int* __restrict__ lact){
    const int cell = blockIdx.x;
    const int dp = threadIdx.x;
    const int l0 = lact[cell];
    const int l1 = lact[cell + 65536];
    uint32_t m = (uint32_t)cell*256u + (uint32_t)(dp*2);
    if (!l0){
        float a = 0.02f*bits_to_normal(threefry_bits(0u, m));
        float bq = 0.02f*bits_to_normal(threefry_bits(0u, m + 1u));
        d_nzh[(size_t)cell*128 + dp] = f2h2(a, bq);
    }
    if (!l1){
        float a = 0.02f*bits_to_normal(threefry_bits(0u, m + 16777216u));
        float bq = 0.02f*bits_to_normal(threefry_bits(0u, m + 16777217u));
        d_nzh[(size_t)(cell+65536)*128 + dp] = f2h2(a, bq);
    }
}

// ================= kB1a: coalesced partial reductions (wide) =================
__global__ void kB1a() {
    const int b = blockIdx.x, t = threadIdx.x;
    if (b < 128){
        int f = b >> 4, c = b & 15;
        const float* p = d_pfsum + (size_t)(f*256 + c*16)*256 + t;
        float S = 0.f;
        #pragma unroll
        for (int i = 0; i < 16; i++) S += p[(size_t)i*256];
        d_SfP[(f*256 + t)*16 + c] = S;
    } else if (b < 160){
        if (t < 128){
            int c = b - 128;
            const float* p = d_pexpout + (size_t)(c*64)*128 + t;
            float s = 0.f;
            #pragma unroll 8
            for (int i = 0; i < 64; i++) s += p[(size_t)i*128];
            d_eorP[t*32 + c] = s;
        }
    } else {
        if (t < 64){
            float s = 0.f;
            #pragma unroll 8
            for (int i = 0; i < 32; i++) s += d_pexpsum[t*32+i];
            d_esP[t] = s;
        } else if (t < 128){
            int c = t - 64; float s = 0.f;
            #pragma unroll 8
            for (int i = 0; i < 32; i++) s += d_ptsum[c*32+i];
            d_tsP[c] = s;
        }
    }
}

// ================= kB2m: merged combine + stats + pred (single block) =================
__global__ __launch_bounds__(1024,1)
void kB2m(const float* __restrict__ head_w, const float* __restrict__ head_b,
          const int* __restrict__ stepp, float* __restrict__ out) {
    __shared__ float sSf[2048], sDf[2048], sEor[128], sEs, sTs;
    const int t = threadIdx.x;
    const int step = *stepp;

    for (int i = t; i < 2048; i += 1024){
        const float* p = d_SfP + i*16;
        float S = 0.f;
        #pragma unroll
        for (int c = 0; c < 16; c++) S += p[c];
        sSf[i] = S;
        sDf[i] = p[0] + p[1] + p[2] + p[3];
    }
    if (t < 128){
        const float* p = d_eorP + t*32;
        float s = 0.f;
        #pragma unroll
        for (int c = 0; c < 32; c++) s += p[c];
        sEor[t] = s;
    } else if (t == 128){
        float s = 0.f;
        #pragma unroll
        for (int c = 0; c < 64; c++) s += d_esP[c];
        sEs = s;
    } else if (t == 129){
        float s = 0.f;
        #pragma unroll
        for (int c = 0; c < 64; c++) s += d_tsP[c];
        sTs = s;
    }
    __syncthreads();

    if (t < 256){
        float Sfv[8];
        #pragma unroll
        for (int f = 0; f < 8; f++) Sfv[f] = sSf[f*256+t];
        float go = 0.f;
        #pragma unroll
        for (int f = 0; f < 8; f++) go += Sfv[f]*(1.0f/16384.0f);
        go *= 0.125f;
        d_go[t] = go;
        float gsum = 0.f;
        #pragma unroll
        for (int f = 0; f < 8; f++){
            float fm = Sfv[f]*(1.0f/16384.0f);
            d_fmean[f*256+t] = fm;
            float Tf = Sfv[f];
            if (step > 5){
                float D = sDf[f*256+t];
                Tf += 0.15f*(4096.0f*go - 0.85f*D - 4096.0f*0.15f*fm);
            }
            gsum += Tf;
        }
        d_gmean[t] = gsum*(1.0f/131072.0f);
    } else if (t >= 256 && t < 384){
        int j = t - 256;
        float inv = 1.0f/sEs;
        float s = head_b[j];
        const float* hw = head_w + j*128;
        for (int k = 0; k < 128; k++) s = fmaf(sEor[k]*inv, hw[k], s);
        out[j] = s;
    } else if (t == 384){
        out[128] = sTs*(1.0f/131072.0f);
    }
}

// ================= kC2: sync/debate/pull + noise(defectors) + clamp =================
__global__ __launch_bounds__(128)
void kC2(const int* __restrict__ lact, const int* __restrict__ stepp,
         float* __restrict__ out) {
    const int cell = blockIdx.x;
    const int dp = threadIdx.x;
    const int step = *stepp;
    const float gm0 = d_gmean[dp*2],  gm1 = d_gmean[dp*2+1];
    const float go0 = d_go[dp*2],     go1 = d_go[dp*2+1];
    #pragma unroll
    for (int half = 0; half < 2; half++){
        int c = cell + half*65536;
        int la = lact[c];
        float coop = (float)la;
        int f = c >> 14;
        float2 hp = h2f2(d_hph[(size_t)c*128 + dp]);
        float2 nz = make_float2(0.f, 0.f);
        if (la == 0) nz = h2f2(d_nzh[(size_t)c*128 + dp]);
        float fm0 = d_fmean[f*256 + dp*2], fm1 = d_fmean[f*256 + dp*2 + 1];
        float v0 = 0.85f*hp.x + 0.15f*fm0;
        float v1 = 0.85f*hp.y + 0.15f*fm1;
        if (step > 5 && (c & 16383) < DC){
            v0 = 0.85f*v0 + 0.15f*go0;
            v1 = 0.85f*v1 + 0.15f*go1;
        }
        v0 += 0.05f*coop*(gm0 - v0);
        v1 += 0.05f*coop*(gm1 - v1);
        v0 += nz.x; v1 += nz.y;
        v0 = fminf(10.0f, fmaxf(-10.0f, v0));
        v1 = fminf(10.0f, fmaxf(-10.0f, v1));
        out[129 + (size_t)c*256 + dp*2]     = v0;
        out[129 + (size_t)c*256 + dp*2 + 1] = v1;
    }
}

// ================= launch (fork kNoise onto a second captured stream) =================
extern "C" void kernel_launch(void* const* d_in, const int* in_sizes, int n_in,
                              void* d_out, int out_size) {
    const float* x       = (const float*)d_in[0];
    const float* payoffs = (const float*)d_in[1];
    const int*   last    = (const int*)d_in[2];
    const int*   step    = (const int*)d_in[3];
    const float* hiddens = (const float*)d_in[4];
    const float* a_w1    = (const float*)d_in[5];
    const float* a_b1    = (const float*)d_in[6];
    const float* a_w2    = (const float*)d_in[7];
    const float* a_b2    = (const float*)d_in[8];
    const float* g_w1    = (const float*)d_in[9];
    const float* g_b1    = (const float*)d_in[10];
    const float* g_w2    = (const float*)d_in[11];
    const float* g_b2    = (const float*)d_in[12];
    const float* gru_wih = (const float*)d_in[13];
    const float* gru_whh = (const float*)d_in[14];
    const float* gru_bih = (const float*)d_in[15];
    const float* gru_bhh = (const float*)d_in[16];
    const float* head_w  = (const float*)d_in[17];
    const float* head_b  = (const float*)d_in[18];
    float* out = (float*)d_out;

    cudaFuncSetAttribute(kA, cudaFuncAttributeMaxDynamicSharedMemorySize, SMW*4);

    cudaStream_t s2;
    cudaEvent_t ev0, ev1;
    cudaStreamCreate(&s2);
    cudaEventCreateWithFlags(&ev0, cudaEventDisableTiming);
    cudaEventCreateWithFlags(&ev1, cudaEventDisableTiming);

    // fork: noise generation depends only on last_action
    cudaEventRecord(ev0, 0);
    cudaStreamWaitEvent(s2, ev0, 0);
    kNoise<<<65536, 128, 0, s2>>>(last);
    cudaEventRecord(ev1, s2);

    // main chain
    kPrep<<<1024, 256>>>(x, a_w1, a_b1, g_w1, g_b1, a_w2, a_b2, g_w2, g_b2,
                         gru_wih, gru_whh, gru_bih, gru_bhh);
    kA<<<NBLK, 256, SMW*4>>>(hiddens, payoffs);
    kB1a<<<161, 256>>>();
    kB2m<<<1, 1024>>>(head_w, head_b, step, out);

    // join: kC2 needs both stats and noise
    cudaStreamWaitEvent(0, ev1, 0);
    kC2<<<65536, 128>>>(last, step, out);
}